// round 4
// baseline (speedup 1.0000x reference)
#include <cuda_runtime.h>

#define EPSF 1e-6f

constexpr int cV = 128, cK = 32, cC = 256;
constexpr int cL = 4, cN = 4096, cF = 16;
constexpr int cE = 8192, cB = 512;
constexpr int cB2 = cB / 2;          // 256 float2 groups per row
constexpr int cB4 = cB / 4;          // 128 float4 groups per row
constexpr int NT   = 512;
constexpr int BPSM = 2;              // blocks/SM guaranteed via launch_bounds
constexpr int GRID = 148 * BPSM;     // 296 persistent blocks
constexpr int NWARP = GRID * NT / 32;  // 4736 warps
constexpr float LN2F = 0.69314718055994530942f;

// ---- scratch (static __device__ per allocation rules) ----
__device__ __align__(16) float d_lwin[cV * cK * cC];   // 4 MB  (log2 domain)
__device__ __align__(16) float d_lwsum[cL * cN * cF];  // 1 MB  (log2 domain)
__device__ __align__(16) float d_lr[cN];               // 16 KB (log2 domain)
__device__ __align__(16) int   d_xT[cV * cB];          // 256 KB transposed inputs
__device__ __align__(16) float d_nmA[cN * cB];         // 8 MB
__device__ __align__(16) float d_nmB[cN * cB];         // 8 MB
__device__ __align__(16) float d_em[cE * cB];          // 16 MB

// ---- grid barrier state ----
__device__ unsigned d_bar_count = 0;
__device__ volatile unsigned d_bar_gen = 0;

// ---- single-instruction MUFU ops ----
__device__ __forceinline__ float ex2(float x) {
    float y; asm("ex2.approx.ftz.f32 %0, %1;" : "=f"(y) : "f"(x)); return y;
}
__device__ __forceinline__ float lg2(float x) {
    float y; asm("lg2.approx.ftz.f32 %0, %1;" : "=f"(y) : "f"(x)); return y;
}

// ==================================================================
// PREP kernel: param normalization (log2 domain) + input transpose
// ==================================================================
__global__ void __launch_bounds__(256) k_prep(const float* __restrict__ ip,
                                              const float* __restrict__ sp,
                                              const float* __restrict__ rp,
                                              const int*   __restrict__ inputs) {
    int b = blockIdx.x;
    if (b < 512) {
        int w    = b * 8 + (threadIdx.x >> 5);
        int lane = threadIdx.x & 31;
        const float* row = ip + w * cC;
        float v[8];
        float m = -1e30f;
#pragma unroll
        for (int i = 0; i < 8; i++) {
            v[i] = lg2(row[lane + i * 32] + EPSF);
            m    = fmaxf(m, v[i]);
        }
#pragma unroll
        for (int o = 16; o; o >>= 1) m = fmaxf(m, __shfl_xor_sync(0xffffffffu, m, o));
        float s = 0.f;
#pragma unroll
        for (int i = 0; i < 8; i++) s += ex2(v[i] - m);
#pragma unroll
        for (int o = 16; o; o >>= 1) s += __shfl_xor_sync(0xffffffffu, s, o);
        float lse = m + lg2(s);
#pragma unroll
        for (int i = 0; i < 8; i++) d_lwin[w * cC + lane + i * 32] = v[i] - lse;
    } else if (b < 576) {
        int r = (b - 512) * 256 + threadIdx.x;
        const float4* s4 = reinterpret_cast<const float4*>(sp) + r * 4;
        float v[16];
#pragma unroll
        for (int i = 0; i < 4; i++) {
            float4 x = s4[i];
            v[i * 4 + 0] = lg2(x.x + EPSF);
            v[i * 4 + 1] = lg2(x.y + EPSF);
            v[i * 4 + 2] = lg2(x.z + EPSF);
            v[i * 4 + 3] = lg2(x.w + EPSF);
        }
        float m = v[0];
#pragma unroll
        for (int i = 1; i < 16; i++) m = fmaxf(m, v[i]);
        float s = 0.f;
#pragma unroll
        for (int i = 0; i < 16; i++) s += ex2(v[i] - m);
        float lse = m + lg2(s);
        float4* dst = reinterpret_cast<float4*>(d_lwsum) + r * 4;
#pragma unroll
        for (int i = 0; i < 4; i++) {
            float4 o;
            o.x = v[i * 4 + 0] - lse; o.y = v[i * 4 + 1] - lse;
            o.z = v[i * 4 + 2] - lse; o.w = v[i * 4 + 3] - lse;
            dst[i] = o;
        }
    } else if (b == 576) {
        __shared__ float red[256];
        int t = threadIdx.x;
        float v[16];
        float m = -1e30f;
#pragma unroll
        for (int i = 0; i < 16; i++) {
            v[i] = lg2(rp[t + i * 256] + EPSF);
            m    = fmaxf(m, v[i]);
        }
        red[t] = m;
        __syncthreads();
        for (int o = 128; o; o >>= 1) {
            if (t < o) red[t] = fmaxf(red[t], red[t + o]);
            __syncthreads();
        }
        m = red[0];
        __syncthreads();
        float s = 0.f;
#pragma unroll
        for (int i = 0; i < 16; i++) s += ex2(v[i] - m);
        red[t] = s;
        __syncthreads();
        for (int o = 128; o; o >>= 1) {
            if (t < o) red[t] += red[t + o];
            __syncthreads();
        }
        float lse = m + lg2(red[0]);
#pragma unroll
        for (int i = 0; i < 16; i++) d_lr[t + i * 256] = v[i] - lse;
    } else {
        int id = (b - 577) * 256 + threadIdx.x;
        for (int i = id; i < cV * cB; i += 64 * 256) {
            int bb = i >> 7;
            int vv = i & 127;
            d_xT[vv * cB + bb] = inputs[i];
        }
    }
}

// ==================================================================
// grid barrier (all GRID blocks resident). __threadfence() makes writes
// visible (pre) and flushes L1D (post via CCTL.IVALL).
// ==================================================================
__device__ __forceinline__ void grid_barrier() {
    __syncthreads();
    if (threadIdx.x == 0) {
        __threadfence();
        unsigned gen = d_bar_gen;
        unsigned t   = atomicAdd(&d_bar_count, 1u);
        if (t == GRID - 1) {
            d_bar_count = 0;
            __threadfence();
            d_bar_gen = gen + 1;
        } else {
            while (d_bar_gen == gen) { __nanosleep(64); }
        }
        __threadfence();
    }
    __syncthreads();
}

// ==================================================================
// PERSISTENT kernel: gather -> 4x (product, sum) -> root LSE
// All layer phases are WARP-autonomous (no block syncs) so the
// scheduler can overlap gather latency freely across 32 warps/SM.
// ==================================================================
__global__ void __launch_bounds__(NT, BPSM) k_persist(const int* __restrict__ pc,
                                                      const int* __restrict__ sci,
                                                      float* __restrict__ out) {
    __shared__ float2 s_red[NT];
    const int t    = threadIdx.x;
    const int lane = t & 31;
    const int wid  = (blockIdx.x * NT + t) >> 5;   // global warp id, 0..NWARP-1

    // ---------- phase 0: input gather -> d_nmA ----------
    {
        const int stride = GRID * NT;
        for (int i = blockIdx.x * NT + t; i < cN * cB; i += stride) {
            int b  = i & (cB - 1);
            int vk = i >> 9;
            int v  = vk >> 5;
            int x  = d_xT[v * cB + b];
            d_nmA[i] = d_lwin[vk * cC + x];
        }
    }
    grid_barrier();

    // ---------- 4 layers ----------
    float* nm_src = d_nmA;
    float* nm_dst = d_nmB;
    for (int l = 0; l < cL; l++) {
        // ---- product layer: warp per (e, batch-quarter) ----
        const int2* pcl = reinterpret_cast<const int2*>(pc + l * cE * 2);
        for (int task = wid; task < cE * 4; task += NWARP) {
            int e = task >> 2;
            int q = task & 3;                      // 0..3 (128-batch quarter)
            int2 c = __ldg(pcl + e);
            int  g = q * 32 + lane;                // float4 group in row
            float4 a = reinterpret_cast<const float4*>(nm_src + c.x * cB)[g];
            float4 b = reinterpret_cast<const float4*>(nm_src + c.y * cB)[g];
            float4 o;
            o.x = a.x + b.x; o.y = a.y + b.y; o.z = a.z + b.z; o.w = a.w + b.w;
            reinterpret_cast<float4*>(d_em)[e * cB4 + g] = o;
        }
        grid_barrier();

        // ---- sum layer: warp per (n, 64-batch chunk), float2/lane ----
        const int*   scil = sci + l * cN * cF;
        const float* wl   = d_lwsum + l * cN * cF;
        const float2* emp = reinterpret_cast<const float2*>(d_em);
        for (int task = wid; task < cN * 8; task += NWARP) {
            int n  = task >> 3;
            int ch = task & 7;
            int off = ch * 32 + lane;              // float2 index in row
            // lane f (and f+16) holds index/weight f
            int   e_my = __ldg(scil + n * cF + (lane & 15));
            float w_my = __ldg(wl   + n * cF + (lane & 15));
            float2 val[cF];
#pragma unroll
            for (int f = 0; f < cF; f++) {
                int   e = __shfl_sync(0xffffffffu, e_my, f);
                float w = __shfl_sync(0xffffffffu, w_my, f);
                float2 x = emp[e * cB2 + off];
                val[f].x = x.x + w; val[f].y = x.y + w;
            }
            float2 m = val[0];
#pragma unroll
            for (int f = 1; f < cF; f++) {
                m.x = fmaxf(m.x, val[f].x);
                m.y = fmaxf(m.y, val[f].y);
            }
            float2 s = make_float2(0.f, 0.f);
#pragma unroll
            for (int f = 0; f < cF; f++) {
                s.x += ex2(val[f].x - m.x);
                s.y += ex2(val[f].y - m.y);
            }
            float2 o;
            o.x = m.x + lg2(s.x);
            o.y = m.y + lg2(s.y);
            reinterpret_cast<float2*>(nm_dst)[n * cB2 + off] = o;
        }
        grid_barrier();

        float* tmp = nm_src; nm_src = nm_dst; nm_dst = tmp;
    }

    // ---------- root: out[b] = ln2 * LSE2_n( nm[n][b] + lr[n] ) ----------
    if (blockIdx.x < cB2) {
        const int g = blockIdx.x;                  // float2 batch group
        const float2* nmp = reinterpret_cast<const float2*>(nm_src);
        float2 v[8];
        float2 m = make_float2(-1e30f, -1e30f);
#pragma unroll
        for (int k = 0; k < 8; k++) {
            int   n  = t + k * NT;
            float lr = __ldg(d_lr + n);
            float2 x = nmp[n * cB2 + g];
            v[k].x = x.x + lr; v[k].y = x.y + lr;
            m.x = fmaxf(m.x, v[k].x); m.y = fmaxf(m.y, v[k].y);
        }
        s_red[t] = m;
        __syncthreads();
        for (int o = NT / 2; o; o >>= 1) {
            if (t < o) {
                float2 a = s_red[t], b2 = s_red[t + o];
                a.x = fmaxf(a.x, b2.x); a.y = fmaxf(a.y, b2.y);
                s_red[t] = a;
            }
            __syncthreads();
        }
        m = s_red[0];
        __syncthreads();
        float2 s = make_float2(0.f, 0.f);
#pragma unroll
        for (int k = 0; k < 8; k++) {
            s.x += ex2(v[k].x - m.x);
            s.y += ex2(v[k].y - m.y);
        }
        s_red[t] = s;
        __syncthreads();
        for (int o = NT / 2; o; o >>= 1) {
            if (t < o) {
                float2 a = s_red[t], b2 = s_red[t + o];
                a.x += b2.x; a.y += b2.y;
                s_red[t] = a;
            }
            __syncthreads();
        }
        if (t == 0) {
            float2 r = s_red[0];
            out[g * 2 + 0] = (m.x + lg2(r.x)) * LN2F;
            out[g * 2 + 1] = (m.y + lg2(r.y)) * LN2F;
        }
    }
}

// ==================================================================
extern "C" void kernel_launch(void* const* d_in, const int* in_sizes, int n_in,
                              void* d_out, int out_size) {
    const int*   inputs = (const int*)d_in[0];    // (B, V)
    const int*   pc     = (const int*)d_in[1];    // (L, E, 2)
    const int*   sci    = (const int*)d_in[2];    // (L, N, F)
    const float* ip     = (const float*)d_in[3];  // (V, K, C)
    const float* sp     = (const float*)d_in[4];  // (L, N, F)
    const float* rp     = (const float*)d_in[5];  // (N,)
    float* out = (float*)d_out;                   // (B,)

    k_prep<<<641, 256>>>(ip, sp, rp, inputs);
    k_persist<<<GRID, NT>>>(pc, sci, out);
}

// round 5
// speedup vs baseline: 1.1003x; 1.1003x over previous
#include <cuda_runtime.h>

#define EPSF 1e-6f

constexpr int cV = 128, cK = 32, cC = 256;
constexpr int cL = 4, cN = 4096, cF = 16;
constexpr int cE = 8192, cB = 512;
constexpr int cB2 = cB / 2;          // 256 float2 groups per row
constexpr int cB4 = cB / 4;          // 128 float4 groups per row
constexpr int NT   = 512;
constexpr int BPSM = 3;              // blocks/SM guaranteed via launch_bounds
constexpr int GRID = 148 * BPSM;     // 444 persistent blocks
constexpr int NWARP = GRID * NT / 32;  // 7104 warps
constexpr float LN2F = 0.69314718055994530942f;

// ---- scratch (static __device__ per allocation rules) ----
__device__ __align__(16) float d_lwin[cV * cK * cC];   // 4 MB  (log2 domain)
__device__ __align__(16) float d_lwsum[cL * cN * cF];  // 1 MB  (log2 domain)
__device__ __align__(16) float d_lr[cN];               // 16 KB (log2 domain)
__device__ __align__(16) int   d_xT[cV * cB];          // 256 KB transposed inputs
__device__ __align__(16) float d_nmA[cN * cB];         // 8 MB
__device__ __align__(16) float d_nmB[cN * cB];         // 8 MB
__device__ __align__(16) float d_em[cE * cB];          // 16 MB

// ---- grid barrier state ----
__device__ unsigned d_bar_count = 0;
__device__ volatile unsigned d_bar_gen = 0;

// ---- single-instruction MUFU ops ----
__device__ __forceinline__ float ex2(float x) {
    float y; asm("ex2.approx.ftz.f32 %0, %1;" : "=f"(y) : "f"(x)); return y;
}
__device__ __forceinline__ float lg2(float x) {
    float y; asm("lg2.approx.ftz.f32 %0, %1;" : "=f"(y) : "f"(x)); return y;
}

// ==================================================================
// PREP kernel: param normalization (log2 domain) + input transpose
// ==================================================================
__global__ void __launch_bounds__(256) k_prep(const float* __restrict__ ip,
                                              const float* __restrict__ sp,
                                              const float* __restrict__ rp,
                                              const int*   __restrict__ inputs) {
    int b = blockIdx.x;
    if (b < 512) {
        int w    = b * 8 + (threadIdx.x >> 5);
        int lane = threadIdx.x & 31;
        const float* row = ip + w * cC;
        float v[8];
        float m = -1e30f;
#pragma unroll
        for (int i = 0; i < 8; i++) {
            v[i] = lg2(row[lane + i * 32] + EPSF);
            m    = fmaxf(m, v[i]);
        }
#pragma unroll
        for (int o = 16; o; o >>= 1) m = fmaxf(m, __shfl_xor_sync(0xffffffffu, m, o));
        float s = 0.f;
#pragma unroll
        for (int i = 0; i < 8; i++) s += ex2(v[i] - m);
#pragma unroll
        for (int o = 16; o; o >>= 1) s += __shfl_xor_sync(0xffffffffu, s, o);
        float lse = m + lg2(s);
#pragma unroll
        for (int i = 0; i < 8; i++) d_lwin[w * cC + lane + i * 32] = v[i] - lse;
    } else if (b < 576) {
        int r = (b - 512) * 256 + threadIdx.x;
        const float4* s4 = reinterpret_cast<const float4*>(sp) + r * 4;
        float v[16];
#pragma unroll
        for (int i = 0; i < 4; i++) {
            float4 x = s4[i];
            v[i * 4 + 0] = lg2(x.x + EPSF);
            v[i * 4 + 1] = lg2(x.y + EPSF);
            v[i * 4 + 2] = lg2(x.z + EPSF);
            v[i * 4 + 3] = lg2(x.w + EPSF);
        }
        float m = v[0];
#pragma unroll
        for (int i = 1; i < 16; i++) m = fmaxf(m, v[i]);
        float s = 0.f;
#pragma unroll
        for (int i = 0; i < 16; i++) s += ex2(v[i] - m);
        float lse = m + lg2(s);
        float4* dst = reinterpret_cast<float4*>(d_lwsum) + r * 4;
#pragma unroll
        for (int i = 0; i < 4; i++) {
            float4 o;
            o.x = v[i * 4 + 0] - lse; o.y = v[i * 4 + 1] - lse;
            o.z = v[i * 4 + 2] - lse; o.w = v[i * 4 + 3] - lse;
            dst[i] = o;
        }
    } else if (b == 576) {
        __shared__ float red[256];
        int t = threadIdx.x;
        float v[16];
        float m = -1e30f;
#pragma unroll
        for (int i = 0; i < 16; i++) {
            v[i] = lg2(rp[t + i * 256] + EPSF);
            m    = fmaxf(m, v[i]);
        }
        red[t] = m;
        __syncthreads();
        for (int o = 128; o; o >>= 1) {
            if (t < o) red[t] = fmaxf(red[t], red[t + o]);
            __syncthreads();
        }
        m = red[0];
        __syncthreads();
        float s = 0.f;
#pragma unroll
        for (int i = 0; i < 16; i++) s += ex2(v[i] - m);
        red[t] = s;
        __syncthreads();
        for (int o = 128; o; o >>= 1) {
            if (t < o) red[t] += red[t + o];
            __syncthreads();
        }
        float lse = m + lg2(red[0]);
#pragma unroll
        for (int i = 0; i < 16; i++) d_lr[t + i * 256] = v[i] - lse;
    } else {
        int id = (b - 577) * 256 + threadIdx.x;
        for (int i = id; i < cV * cB; i += 64 * 256) {
            int bb = i >> 7;
            int vv = i & 127;
            d_xT[vv * cB + bb] = inputs[i];
        }
    }
}

// ==================================================================
// grid barrier (all GRID blocks resident). __threadfence() makes writes
// visible (pre) and flushes L1D (post via CCTL.IVALL).
// ==================================================================
__device__ __forceinline__ void grid_barrier() {
    __syncthreads();
    if (threadIdx.x == 0) {
        __threadfence();
        unsigned gen = d_bar_gen;
        unsigned t   = atomicAdd(&d_bar_count, 1u);
        if (t == GRID - 1) {
            d_bar_count = 0;
            __threadfence();
            d_bar_gen = gen + 1;
        } else {
            while (d_bar_gen == gen) { __nanosleep(64); }
        }
        __threadfence();
    }
    __syncthreads();
}

// ==================================================================
// PERSISTENT kernel. 512 thr/block, 3 blocks/SM -> 48 warps/SM.
// Sum layer uses split-F LSE (halves of 8) to halve val[] registers.
// ==================================================================
__global__ void __launch_bounds__(NT, BPSM) k_persist(const int* __restrict__ pc,
                                                      const int* __restrict__ sci,
                                                      float* __restrict__ out) {
    __shared__ float2 s_red[NT];
    const int t    = threadIdx.x;
    const int lane = t & 31;
    const int wid  = (blockIdx.x * NT + t) >> 5;   // global warp id

    // ---------- phase 0: input gather -> d_nmA ----------
    {
        const int stride = GRID * NT;
        for (int i = blockIdx.x * NT + t; i < cN * cB; i += stride) {
            int b  = i & (cB - 1);
            int vk = i >> 9;
            int v  = vk >> 5;
            int x  = d_xT[v * cB + b];
            d_nmA[i] = d_lwin[vk * cC + x];
        }
    }
    grid_barrier();

    // ---------- 4 layers ----------
    float* nm_src = d_nmA;
    float* nm_dst = d_nmB;
    for (int l = 0; l < cL; l++) {
        // ---- product layer: warp per (e, batch-quarter), float4 ----
        const int2* pcl = reinterpret_cast<const int2*>(pc + l * cE * 2);
        for (int task = wid; task < cE * 4; task += NWARP) {
            int e = task >> 2;
            int q = task & 3;
            int2 c = __ldg(pcl + e);
            int  g = q * 32 + lane;
            float4 a = reinterpret_cast<const float4*>(nm_src + c.x * cB)[g];
            float4 b = reinterpret_cast<const float4*>(nm_src + c.y * cB)[g];
            float4 o;
            o.x = a.x + b.x; o.y = a.y + b.y; o.z = a.z + b.z; o.w = a.w + b.w;
            reinterpret_cast<float4*>(d_em)[e * cB4 + g] = o;
        }
        grid_barrier();

        // ---- sum layer: warp per (n, 64-batch chunk), split-F LSE ----
        const int*   scil = sci + l * cN * cF;
        const float* wl   = d_lwsum + l * cN * cF;
        const float2* emp = reinterpret_cast<const float2*>(d_em);
        for (int task = wid; task < cN * 8; task += NWARP) {
            int n   = task >> 3;
            int off = ((task & 7) << 5) + lane;    // float2 index in row
            int   e_my = __ldg(scil + n * cF + (lane & 15));
            float w_my = __ldg(wl   + n * cF + (lane & 15));
            float2 val[8];

            // ---- half A: f = 0..7 ----
#pragma unroll
            for (int f = 0; f < 8; f++) {
                int   e = __shfl_sync(0xffffffffu, e_my, f);
                float w = __shfl_sync(0xffffffffu, w_my, f);
                float2 x = emp[e * cB2 + off];
                val[f].x = x.x + w; val[f].y = x.y + w;
            }
            float2 mA = val[0];
#pragma unroll
            for (int f = 1; f < 8; f++) {
                mA.x = fmaxf(mA.x, val[f].x);
                mA.y = fmaxf(mA.y, val[f].y);
            }
            float2 sA = make_float2(0.f, 0.f);
#pragma unroll
            for (int f = 0; f < 8; f++) {
                sA.x += ex2(val[f].x - mA.x);
                sA.y += ex2(val[f].y - mA.y);
            }

            // ---- half B: f = 8..15 (reuses val regs; loads overlap A's exp) ----
#pragma unroll
            for (int f = 0; f < 8; f++) {
                int   e = __shfl_sync(0xffffffffu, e_my, f + 8);
                float w = __shfl_sync(0xffffffffu, w_my, f + 8);
                float2 x = emp[e * cB2 + off];
                val[f].x = x.x + w; val[f].y = x.y + w;
            }
            float2 mB = val[0];
#pragma unroll
            for (int f = 1; f < 8; f++) {
                mB.x = fmaxf(mB.x, val[f].x);
                mB.y = fmaxf(mB.y, val[f].y);
            }
            float2 sB = make_float2(0.f, 0.f);
#pragma unroll
            for (int f = 0; f < 8; f++) {
                sB.x += ex2(val[f].x - mB.x);
                sB.y += ex2(val[f].y - mB.y);
            }

            // ---- combine: LSE = m + lg2(sA*2^(mA-m) + sB*2^(mB-m)) ----
            float2 o;
            {
                float m  = fmaxf(mA.x, mB.x);
                float s  = sA.x * ex2(mA.x - m) + sB.x * ex2(mB.x - m);
                o.x = m + lg2(s);
                m  = fmaxf(mA.y, mB.y);
                s  = sA.y * ex2(mA.y - m) + sB.y * ex2(mB.y - m);
                o.y = m + lg2(s);
            }
            reinterpret_cast<float2*>(nm_dst)[n * cB2 + off] = o;
        }
        grid_barrier();

        float* tmp = nm_src; nm_src = nm_dst; nm_dst = tmp;
    }

    // ---------- root: out[b] = ln2 * LSE2_n( nm[n][b] + lr[n] ) ----------
    if (blockIdx.x < cB2) {
        const int g = blockIdx.x;
        const float2* nmp = reinterpret_cast<const float2*>(nm_src);
        float2 v[8];
        float2 m = make_float2(-1e30f, -1e30f);
#pragma unroll
        for (int k = 0; k < 8; k++) {
            int   n  = t + k * NT;
            float lr = __ldg(d_lr + n);
            float2 x = nmp[n * cB2 + g];
            v[k].x = x.x + lr; v[k].y = x.y + lr;
            m.x = fmaxf(m.x, v[k].x); m.y = fmaxf(m.y, v[k].y);
        }
        s_red[t] = m;
        __syncthreads();
        for (int o = NT / 2; o; o >>= 1) {
            if (t < o) {
                float2 a = s_red[t], b2 = s_red[t + o];
                a.x = fmaxf(a.x, b2.x); a.y = fmaxf(a.y, b2.y);
                s_red[t] = a;
            }
            __syncthreads();
        }
        m = s_red[0];
        __syncthreads();
        float2 s = make_float2(0.f, 0.f);
#pragma unroll
        for (int k = 0; k < 8; k++) {
            s.x += ex2(v[k].x - m.x);
            s.y += ex2(v[k].y - m.y);
        }
        s_red[t] = s;
        __syncthreads();
        for (int o = NT / 2; o; o >>= 1) {
            if (t < o) {
                float2 a = s_red[t], b2 = s_red[t + o];
                a.x += b2.x; a.y += b2.y;
                s_red[t] = a;
            }
            __syncthreads();
        }
        if (t == 0) {
            float2 r = s_red[0];
            out[g * 2 + 0] = (m.x + lg2(r.x)) * LN2F;
            out[g * 2 + 1] = (m.y + lg2(r.y)) * LN2F;
        }
    }
}

// ==================================================================
extern "C" void kernel_launch(void* const* d_in, const int* in_sizes, int n_in,
                              void* d_out, int out_size) {
    const int*   inputs = (const int*)d_in[0];    // (B, V)
    const int*   pc     = (const int*)d_in[1];    // (L, E, 2)
    const int*   sci    = (const int*)d_in[2];    // (L, N, F)
    const float* ip     = (const float*)d_in[3];  // (V, K, C)
    const float* sp     = (const float*)d_in[4];  // (L, N, F)
    const float* rp     = (const float*)d_in[5];  // (N,)
    float* out = (float*)d_out;                   // (B,)

    k_prep<<<641, 256>>>(ip, sp, rp, inputs);
    k_persist<<<GRID, NT>>>(pc, sci, out);
}

// round 6
// speedup vs baseline: 1.1227x; 1.0204x over previous
#include <cuda_runtime.h>

#define EPSF 1e-6f

constexpr int cV = 128, cK = 32, cC = 256;
constexpr int cL = 4, cN = 4096, cF = 16;
constexpr int cE = 8192, cB = 512;
constexpr int cB4 = cB / 4;            // 128 float4 groups per row
constexpr int NT   = 512;
constexpr int BPSM = 3;                // blocks/SM via launch_bounds
constexpr int GRID = 148 * BPSM;       // 444 persistent blocks
constexpr int NWARP = GRID * NT / 32;  // 7104 warps
constexpr float LN2F = 0.69314718055994530942f;

// ---- scratch (static __device__ per allocation rules) ----
__device__ __align__(16) float d_lwin[cV * cK * cC];   // 4 MB (log2 domain)
__device__ __align__(16) int2  d_pw[cL * cN * cF];     // 2 MB {e*cB4, W linear}
__device__ __align__(16) float d_R[cN];                // 16 KB linear root weights
__device__ __align__(16) int   d_xT[cV * cB];          // 256 KB transposed inputs
__device__ __align__(16) float d_nmA[cN * cB];         // 8 MB
__device__ __align__(16) float d_nmB[cN * cB];         // 8 MB
__device__ __align__(16) float d_em[cE * cB];          // 16 MB

// ---- grid barrier state ----
__device__ unsigned d_bar_count = 0;
__device__ volatile unsigned d_bar_gen = 0;

// ---- single-instruction MUFU ops ----
__device__ __forceinline__ float ex2(float x) {
    float y; asm("ex2.approx.ftz.f32 %0, %1;" : "=f"(y) : "f"(x)); return y;
}
__device__ __forceinline__ float lg2(float x) {
    float y; asm("lg2.approx.ftz.f32 %0, %1;" : "=f"(y) : "f"(x)); return y;
}

// ==================================================================
// PREP: lwin (log2-normalized), packed sum weights (LINEAR domain),
// linear root weights, input transpose.
// ==================================================================
__global__ void __launch_bounds__(256) k_prep(const float* __restrict__ ip,
                                              const float* __restrict__ sp,
                                              const float* __restrict__ rp,
                                              const int*   __restrict__ inputs,
                                              const int*   __restrict__ sci) {
    int b = blockIdx.x;
    if (b < 512) {
        // --- input params: one warp per (v,k) row of C=256, log2 domain ---
        int w    = b * 8 + (threadIdx.x >> 5);
        int lane = threadIdx.x & 31;
        const float* row = ip + w * cC;
        float v[8];
        float m = -1e30f;
#pragma unroll
        for (int i = 0; i < 8; i++) {
            v[i] = lg2(row[lane + i * 32] + EPSF);
            m    = fmaxf(m, v[i]);
        }
#pragma unroll
        for (int o = 16; o; o >>= 1) m = fmaxf(m, __shfl_xor_sync(0xffffffffu, m, o));
        float s = 0.f;
#pragma unroll
        for (int i = 0; i < 8; i++) s += ex2(v[i] - m);
#pragma unroll
        for (int o = 16; o; o >>= 1) s += __shfl_xor_sync(0xffffffffu, s, o);
        float lse = m + lg2(s);
#pragma unroll
        for (int i = 0; i < 8; i++) d_lwin[w * cC + lane + i * 32] = v[i] - lse;
    } else if (b < 576) {
        // --- sum params: one thread per (l,n): pack {e*cB4, W} ---
        int r = (b - 512) * 256 + threadIdx.x;   // 0..L*N-1
        const float* spr  = sp  + r * cF;
        const int*   scir = sci + r * cF;
        float w[cF];
        float tot = 0.f;
#pragma unroll
        for (int f = 0; f < cF; f++) { w[f] = spr[f] + EPSF; tot += w[f]; }
        float inv = 1.f / tot;
        int2* dst = d_pw + r * cF;
#pragma unroll
        for (int f = 0; f < cF; f++)
            dst[f] = make_int2(scir[f] * cB4, __float_as_int(w[f] * inv));
    } else if (b == 576) {
        // --- root params: linear normalize over N=4096 ---
        __shared__ float red[256];
        int t = threadIdx.x;
        float v[16];
        float s = 0.f;
#pragma unroll
        for (int i = 0; i < 16; i++) {
            v[i] = rp[t + i * 256] + EPSF;
            s += v[i];
        }
        red[t] = s;
        __syncthreads();
        for (int o = 128; o; o >>= 1) {
            if (t < o) red[t] += red[t + o];
            __syncthreads();
        }
        float inv = 1.f / red[0];
#pragma unroll
        for (int i = 0; i < 16; i++) d_R[t + i * 256] = v[i] * inv;
    } else {
        // --- transpose inputs (B,V) -> xT (V,B) ---
        int id = (b - 577) * 256 + threadIdx.x;
        for (int i = id; i < cV * cB; i += 64 * 256) {
            int bb = i >> 7;
            int vv = i & 127;
            d_xT[vv * cB + bb] = inputs[i];
        }
    }
}

// ==================================================================
// grid barrier (all GRID blocks resident).
// ==================================================================
__device__ __forceinline__ void grid_barrier() {
    __syncthreads();
    if (threadIdx.x == 0) {
        __threadfence();
        unsigned gen = d_bar_gen;
        unsigned t   = atomicAdd(&d_bar_count, 1u);
        if (t == GRID - 1) {
            d_bar_count = 0;
            __threadfence();
            d_bar_gen = gen + 1;
        } else {
            while (d_bar_gen == gen) { __nanosleep(64); }
        }
        __threadfence();
    }
    __syncthreads();
}

// ==================================================================
// PERSISTENT kernel: gather -> 4x (product, sum) -> root LSE.
// Sum layer: s = sum_f W_f * 2^(x_f - x_0); out = x_0 + lg2(s).
// ==================================================================
__global__ void __launch_bounds__(NT, BPSM) k_persist(const int* __restrict__ pc,
                                                      float* __restrict__ out) {
    __shared__ float4 s_m[NT];
    __shared__ float4 s_s[NT];
    const int t    = threadIdx.x;
    const int lane = t & 31;
    const int wid  = (blockIdx.x * NT + t) >> 5;   // global warp id

    // ---------- phase 0: input gather -> d_nmA ----------
    {
        const int stride = GRID * NT;
        for (int i = blockIdx.x * NT + t; i < cN * cB; i += stride) {
            int b  = i & (cB - 1);
            int vk = i >> 9;
            int v  = vk >> 5;
            int x  = d_xT[v * cB + b];
            d_nmA[i] = d_lwin[vk * cC + x];
        }
    }
    grid_barrier();

    // ---------- 4 layers ----------
    float* nm_src = d_nmA;
    float* nm_dst = d_nmB;
    for (int l = 0; l < cL; l++) {
        // ---- product layer: warp per (e, batch-quarter), float4 ----
        const int2* pcl = reinterpret_cast<const int2*>(pc + l * cE * 2);
        for (int task = wid; task < cE * 4; task += NWARP) {
            int e = task >> 2;
            int g = ((task & 3) << 5) + lane;
            int2 c = __ldg(pcl + e);
            float4 a = reinterpret_cast<const float4*>(nm_src + c.x * cB)[g];
            float4 b = reinterpret_cast<const float4*>(nm_src + c.y * cB)[g];
            float4 o;
            o.x = a.x + b.x; o.y = a.y + b.y; o.z = a.z + b.z; o.w = a.w + b.w;
            reinterpret_cast<float4*>(d_em)[e * cB4 + g] = o;
        }
        grid_barrier();

        // ---- sum layer: warp per (n, batch-quarter), float4/lane ----
        const int2*  pwl = d_pw + l * cN * cF;
        const float4* emp = reinterpret_cast<const float4*>(d_em);
        for (int task = wid; task < cN * 4; task += NWARP) {
            int n = task >> 2;
            int g = ((task & 3) << 5) + lane;
            const int2* pwp = pwl + n * cF;

            int2  p0 = __ldg(pwp);
            float W0 = __int_as_float(p0.y);
            float4 m = emp[p0.x + g];          // shift = first child's value
            float4 s = make_float4(W0, W0, W0, W0);   // W0 * 2^0
#pragma unroll
            for (int f = 1; f < cF; f++) {
                int2  p = __ldg(pwp + f);
                float W = __int_as_float(p.y);
                float4 x = emp[p.x + g];
                s.x += W * ex2(x.x - m.x);
                s.y += W * ex2(x.y - m.y);
                s.z += W * ex2(x.z - m.z);
                s.w += W * ex2(x.w - m.w);
            }
            float4 o;
            o.x = m.x + lg2(s.x);
            o.y = m.y + lg2(s.y);
            o.z = m.z + lg2(s.z);
            o.w = m.w + lg2(s.w);
            reinterpret_cast<float4*>(nm_dst)[n * cB4 + g] = o;
        }
        grid_barrier();

        float* tmp = nm_src; nm_src = nm_dst; nm_dst = tmp;
    }

    // ---------- root: out[b] = ln2 * (m + lg2(sum_n R_n 2^(x_nb - m))) ----------
    if (blockIdx.x < cB4) {
        const int g = blockIdx.x;              // float4 batch group
        const float4* nmp = reinterpret_cast<const float4*>(nm_src);

        // per-thread pass with per-thread shift m_t = first value
        float R0 = __ldg(d_R + t);
        float4 m = nmp[t * cB4 + g];
        float4 s = make_float4(R0, R0, R0, R0);
#pragma unroll
        for (int k = 1; k < cN / NT; k++) {
            int   n = t + k * NT;
            float R = __ldg(d_R + n);
            float4 x = nmp[n * cB4 + g];
            s.x += R * ex2(x.x - m.x);
            s.y += R * ex2(x.y - m.y);
            s.z += R * ex2(x.z - m.z);
            s.w += R * ex2(x.w - m.w);
        }
        s_m[t] = m; s_s[t] = s;
        __syncthreads();
        // tree-combine (m,s) pairs: s = s1*2^(m1-m) + s2*2^(m2-m), m = max
        for (int o = NT / 2; o; o >>= 1) {
            if (t < o) {
                float4 m1 = s_m[t], m2 = s_m[t + o];
                float4 s1 = s_s[t], s2 = s_s[t + o];
                float4 mm, ss;
                mm.x = fmaxf(m1.x, m2.x);
                mm.y = fmaxf(m1.y, m2.y);
                mm.z = fmaxf(m1.z, m2.z);
                mm.w = fmaxf(m1.w, m2.w);
                ss.x = s1.x * ex2(m1.x - mm.x) + s2.x * ex2(m2.x - mm.x);
                ss.y = s1.y * ex2(m1.y - mm.y) + s2.y * ex2(m2.y - mm.y);
                ss.z = s1.z * ex2(m1.z - mm.z) + s2.z * ex2(m2.z - mm.z);
                ss.w = s1.w * ex2(m1.w - mm.w) + s2.w * ex2(m2.w - mm.w);
                s_m[t] = mm; s_s[t] = ss;
            }
            __syncthreads();
        }
        if (t == 0) {
            float4 m0 = s_m[0], s0 = s_s[0];
            out[g * 4 + 0] = (m0.x + lg2(s0.x)) * LN2F;
            out[g * 4 + 1] = (m0.y + lg2(s0.y)) * LN2F;
            out[g * 4 + 2] = (m0.z + lg2(s0.z)) * LN2F;
            out[g * 4 + 3] = (m0.w + lg2(s0.w)) * LN2F;
        }
    }
}

// ==================================================================
extern "C" void kernel_launch(void* const* d_in, const int* in_sizes, int n_in,
                              void* d_out, int out_size) {
    const int*   inputs = (const int*)d_in[0];    // (B, V)
    const int*   pc     = (const int*)d_in[1];    // (L, E, 2)
    const int*   sci    = (const int*)d_in[2];    // (L, N, F)
    const float* ip     = (const float*)d_in[3];  // (V, K, C)
    const float* sp     = (const float*)d_in[4];  // (L, N, F)
    const float* rp     = (const float*)d_in[5];  // (N,)
    float* out = (float*)d_out;                   // (B,)

    k_prep<<<641, 256>>>(ip, sp, rp, inputs, sci);
    k_persist<<<GRID, NT>>>(pc, out);
}

// round 7
// speedup vs baseline: 1.1492x; 1.0235x over previous
#include <cuda_runtime.h>

#define EPSF 1e-6f

constexpr int cV = 128, cK = 32, cC = 256;
constexpr int cL = 4, cN = 4096, cF = 16;
constexpr int cE = 8192, cB = 512;
constexpr int cB4 = cB / 4;            // 128 float4 groups per row
constexpr int NT   = 512;
constexpr int BPSM = 3;                // blocks/SM via launch_bounds
constexpr int GRID = 148 * BPSM;       // 444 persistent blocks
constexpr int NWARP = GRID * NT / 32;  // 7104 warps
constexpr float LN2F = 0.69314718055994530942f;

// ---- scratch (static __device__ per allocation rules) ----
__device__ __align__(16) float d_lwin[cV * cK * cC];   // 4 MB (log2 domain)
__device__ __align__(16) int4  d_fw[cL * cN * cF];     // 4 MB {c0*cB4, c1*cB4, W, 0}
__device__ __align__(16) float d_R[cN];                // 16 KB linear root weights
__device__ __align__(16) int   d_xT[cV * cB];          // 256 KB transposed inputs
__device__ __align__(16) float d_nmA[cN * cB];         // 8 MB
__device__ __align__(16) float d_nmB[cN * cB];         // 8 MB

// ---- grid barrier state ----
__device__ unsigned d_bar_count = 0;
__device__ volatile unsigned d_bar_gen = 0;

// ---- single-instruction MUFU ops ----
__device__ __forceinline__ float ex2(float x) {
    float y; asm("ex2.approx.ftz.f32 %0, %1;" : "=f"(y) : "f"(x)); return y;
}
__device__ __forceinline__ float lg2(float x) {
    float y; asm("lg2.approx.ftz.f32 %0, %1;" : "=f"(y) : "f"(x)); return y;
}

// ==================================================================
// PREP: lwin (log2-normalized), FUSED sum tables {c0,c1,W}, linear
// root weights, input transpose.
// ==================================================================
__global__ void __launch_bounds__(256) k_prep(const float* __restrict__ ip,
                                              const float* __restrict__ sp,
                                              const float* __restrict__ rp,
                                              const int*   __restrict__ inputs,
                                              const int*   __restrict__ sci,
                                              const int*   __restrict__ pc) {
    int b = blockIdx.x;
    if (b < 512) {
        // --- input params: one warp per (v,k) row of C=256, log2 domain ---
        int w    = b * 8 + (threadIdx.x >> 5);
        int lane = threadIdx.x & 31;
        const float* row = ip + w * cC;
        float v[8];
        float m = -1e30f;
#pragma unroll
        for (int i = 0; i < 8; i++) {
            v[i] = lg2(row[lane + i * 32] + EPSF);
            m    = fmaxf(m, v[i]);
        }
#pragma unroll
        for (int o = 16; o; o >>= 1) m = fmaxf(m, __shfl_xor_sync(0xffffffffu, m, o));
        float s = 0.f;
#pragma unroll
        for (int i = 0; i < 8; i++) s += ex2(v[i] - m);
#pragma unroll
        for (int o = 16; o; o >>= 1) s += __shfl_xor_sync(0xffffffffu, s, o);
        float lse = m + lg2(s);
#pragma unroll
        for (int i = 0; i < 8; i++) d_lwin[w * cC + lane + i * 32] = v[i] - lse;
    } else if (b < 576) {
        // --- fused sum tables: one thread per (l,n) ---
        int r = (b - 512) * 256 + threadIdx.x;   // 0..L*N-1
        int l = r / cN;
        const float* spr  = sp  + r * cF;
        const int*   scir = sci + r * cF;
        const int2*  pcl  = reinterpret_cast<const int2*>(pc) + l * cE;
        float w[cF];
        float tot = 0.f;
#pragma unroll
        for (int f = 0; f < cF; f++) { w[f] = spr[f] + EPSF; tot += w[f]; }
        float inv = 1.f / tot;
        int4* dst = d_fw + r * cF;
#pragma unroll
        for (int f = 0; f < cF; f++) {
            int2 c = pcl[scir[f]];
            dst[f] = make_int4(c.x * cB4, c.y * cB4, __float_as_int(w[f] * inv), 0);
        }
    } else if (b == 576) {
        // --- root params: linear normalize over N=4096 ---
        __shared__ float red[256];
        int t = threadIdx.x;
        float v[16];
        float s = 0.f;
#pragma unroll
        for (int i = 0; i < 16; i++) {
            v[i] = rp[t + i * 256] + EPSF;
            s += v[i];
        }
        red[t] = s;
        __syncthreads();
        for (int o = 128; o; o >>= 1) {
            if (t < o) red[t] += red[t + o];
            __syncthreads();
        }
        float inv = 1.f / red[0];
#pragma unroll
        for (int i = 0; i < 16; i++) d_R[t + i * 256] = v[i] * inv;
    } else {
        // --- transpose inputs (B,V) -> xT (V,B) ---
        int id = (b - 577) * 256 + threadIdx.x;
        for (int i = id; i < cV * cB; i += 64 * 256) {
            int bb = i >> 7;
            int vv = i & 127;
            d_xT[vv * cB + bb] = inputs[i];
        }
    }
}

// ==================================================================
// grid barrier (all GRID blocks resident).
// ==================================================================
__device__ __forceinline__ void grid_barrier() {
    __syncthreads();
    if (threadIdx.x == 0) {
        __threadfence();
        unsigned gen = d_bar_gen;
        unsigned t   = atomicAdd(&d_bar_count, 1u);
        if (t == GRID - 1) {
            d_bar_count = 0;
            __threadfence();
            d_bar_gen = gen + 1;
        } else {
            while (d_bar_gen == gen) { __nanosleep(64); }
        }
        __threadfence();
    }
    __syncthreads();
}

// ==================================================================
// PERSISTENT kernel: gather -> 4x FUSED(product+sum) -> root LSE.
// Fused layer: x_f = nm[c0_f] + nm[c1_f] (gathered directly),
//              s = sum_f W_f * 2^(x_f - x_0); out = x_0 + lg2(s).
// ==================================================================
__global__ void __launch_bounds__(NT, BPSM) k_persist(float* __restrict__ out) {
    __shared__ float4 s_m[NT];
    __shared__ float4 s_s[NT];
    const int t    = threadIdx.x;
    const int lane = t & 31;
    const int wid  = (blockIdx.x * NT + t) >> 5;   // global warp id

    // ---------- phase 0: input gather -> d_nmA ----------
    {
        const int stride = GRID * NT;
        for (int i = blockIdx.x * NT + t; i < cN * cB; i += stride) {
            int b  = i & (cB - 1);
            int vk = i >> 9;
            int v  = vk >> 5;
            int x  = d_xT[v * cB + b];
            d_nmA[i] = d_lwin[vk * cC + x];
        }
    }
    grid_barrier();

    // ---------- 4 fused layers ----------
    float* nm_src = d_nmA;
    float* nm_dst = d_nmB;
    for (int l = 0; l < cL; l++) {
        const int4*   fwl = d_fw + l * cN * cF;
        const float4* nmp = reinterpret_cast<const float4*>(nm_src);
        for (int task = wid; task < cN * 4; task += NWARP) {
            int n = task >> 2;
            int g = ((task & 3) << 5) + lane;
            const int4* fwp = fwl + n * cF;

            int4 p0 = __ldg(fwp);
            float4 a0 = nmp[p0.x + g];
            float4 b0 = nmp[p0.y + g];
            float4 m;                       // shift = first child's value
            m.x = a0.x + b0.x; m.y = a0.y + b0.y;
            m.z = a0.z + b0.z; m.w = a0.w + b0.w;
            float W0 = __int_as_float(p0.z);
            float4 s = make_float4(W0, W0, W0, W0);
#pragma unroll
            for (int f = 1; f < cF; f++) {
                int4 p = __ldg(fwp + f);
                float4 a = nmp[p.x + g];
                float4 b = nmp[p.y + g];
                float  W = __int_as_float(p.z);
                s.x += W * ex2(a.x + b.x - m.x);
                s.y += W * ex2(a.y + b.y - m.y);
                s.z += W * ex2(a.z + b.z - m.z);
                s.w += W * ex2(a.w + b.w - m.w);
            }
            float4 o;
            o.x = m.x + lg2(s.x);
            o.y = m.y + lg2(s.y);
            o.z = m.z + lg2(s.z);
            o.w = m.w + lg2(s.w);
            reinterpret_cast<float4*>(nm_dst)[n * cB4 + g] = o;
        }
        grid_barrier();

        float* tmp = nm_src; nm_src = nm_dst; nm_dst = tmp;
    }

    // ---------- root: out[b] = ln2 * (m + lg2(sum_n R_n 2^(x_nb - m))) ----------
    if (blockIdx.x < cB4) {
        const int g = blockIdx.x;              // float4 batch group
        const float4* nmp = reinterpret_cast<const float4*>(nm_src);

        float R0 = __ldg(d_R + t);
        float4 m = nmp[t * cB4 + g];
        float4 s = make_float4(R0, R0, R0, R0);
#pragma unroll
        for (int k = 1; k < cN / NT; k++) {
            int   n = t + k * NT;
            float R = __ldg(d_R + n);
            float4 x = nmp[n * cB4 + g];
            s.x += R * ex2(x.x - m.x);
            s.y += R * ex2(x.y - m.y);
            s.z += R * ex2(x.z - m.z);
            s.w += R * ex2(x.w - m.w);
        }
        s_m[t] = m; s_s[t] = s;
        __syncthreads();
        for (int o = NT / 2; o; o >>= 1) {
            if (t < o) {
                float4 m1 = s_m[t], m2 = s_m[t + o];
                float4 s1 = s_s[t], s2 = s_s[t + o];
                float4 mm, ss;
                mm.x = fmaxf(m1.x, m2.x);
                mm.y = fmaxf(m1.y, m2.y);
                mm.z = fmaxf(m1.z, m2.z);
                mm.w = fmaxf(m1.w, m2.w);
                ss.x = s1.x * ex2(m1.x - mm.x) + s2.x * ex2(m2.x - mm.x);
                ss.y = s1.y * ex2(m1.y - mm.y) + s2.y * ex2(m2.y - mm.y);
                ss.z = s1.z * ex2(m1.z - mm.z) + s2.z * ex2(m2.z - mm.z);
                ss.w = s1.w * ex2(m1.w - mm.w) + s2.w * ex2(m2.w - mm.w);
                s_m[t] = mm; s_s[t] = ss;
            }
            __syncthreads();
        }
        if (t == 0) {
            float4 m0 = s_m[0], s0 = s_s[0];
            out[g * 4 + 0] = (m0.x + lg2(s0.x)) * LN2F;
            out[g * 4 + 1] = (m0.y + lg2(s0.y)) * LN2F;
            out[g * 4 + 2] = (m0.z + lg2(s0.z)) * LN2F;
            out[g * 4 + 3] = (m0.w + lg2(s0.w)) * LN2F;
        }
    }
}

// ==================================================================
extern "C" void kernel_launch(void* const* d_in, const int* in_sizes, int n_in,
                              void* d_out, int out_size) {
    const int*   inputs = (const int*)d_in[0];    // (B, V)
    const int*   pc     = (const int*)d_in[1];    // (L, E, 2)
    const int*   sci    = (const int*)d_in[2];    // (L, N, F)
    const float* ip     = (const float*)d_in[3];  // (V, K, C)
    const float* sp     = (const float*)d_in[4];  // (L, N, F)
    const float* rp     = (const float*)d_in[5];  // (N,)
    float* out = (float*)d_out;                   // (B,)

    k_prep<<<641, 256>>>(ip, sp, rp, inputs, sci, pc);
    k_persist<<<GRID, NT>>>(out);
}